// round 12
// baseline (speedup 1.0000x reference)
#include <cuda_runtime.h>
#include <cstdint>

#define N_NODES 50000
#define N_EDGES 800000
#define DIM     128
#define NG      64
#define OUTD    16
#define SCAN_B  1024
#define NBLK    ((N_NODES + SCAN_B - 1) / SCAN_B)   // 49

// ---------------- scratch (static device globals; no allocation) ----------------
__device__ __align__(16) int   g_src[N_EDGES];
__device__ __align__(16) int   g_dst[N_EDGES];
__device__ __align__(16) int   g_esrc[N_EDGES];     // bucketed-by-dst src list
__device__ __align__(16) int   g_batch[N_NODES];
__device__ __align__(16) int   g_ecnt[N_NODES];     // in-degree (edges only)
__device__ __align__(16) int   g_off[N_NODES];      // block-local exclusive scan
__device__ __align__(16) int   g_rowstart[N_NODES]; // final CSR row start
__device__ __align__(16) int   g_cursor[N_NODES];   // bucket-fill cursors
__device__ int   g_bsum[NBLK];
__device__ int   g_bo[NBLK];
__device__ __align__(128) float g_bufA[(size_t)N_NODES * DIM];  // h*dis (gather source)
__device__ __align__(128) float g_bufB[(size_t)N_NODES * DIM];  // layer output
__device__ __align__(16) float g_sums[NG * DIM];
__device__ __align__(16) float g_cnts[NG];
__device__ int g_is64;

// ---------------- init + dtype detect ----------------
__global__ void k_init(const void* ei) {
    int i  = blockIdx.x * blockDim.x + threadIdx.x;
    if (i == 0) {
        const unsigned long long* p = (const unsigned long long*)ei;
        bool is64 = true;
        for (int j = 0; j < 8; j++)
            if (p[j] >= (unsigned long long)N_NODES) is64 = false;
        g_is64 = is64 ? 1 : 0;
    }
    int st = gridDim.x * blockDim.x;
    for (int n = i; n < N_NODES; n += st) g_ecnt[n] = 0;
    for (int n = i; n < NG * DIM; n += st) g_sums[n] = 0.0f;
    for (int n = i; n < NG; n += st) g_cnts[n] = 0.0f;
}

// ---------------- convert indices + degree histogram + graph counts ----------------
__global__ void k_convert(const void* ei, const void* batch) {
    int i  = blockIdx.x * blockDim.x + threadIdx.x;
    int st = gridDim.x * blockDim.x;
    const bool is64 = (g_is64 != 0);
    for (int e = i; e < N_EDGES; e += st) {
        int s, d;
        if (is64) {
            s = (int)((const long long*)ei)[e];
            d = (int)((const long long*)ei)[N_EDGES + e];
        } else {
            s = ((const int*)ei)[e];
            d = ((const int*)ei)[N_EDGES + e];
        }
        g_src[e] = s;
        g_dst[e] = d;
        atomicAdd(&g_ecnt[d], 1);
    }
    for (int n = i; n < N_NODES; n += st) {
        int b = is64 ? (int)((const long long*)batch)[n]
                     : ((const int*)batch)[n];
        g_batch[n] = b;
        atomicAdd(&g_cnts[b], 1.0f);
    }
}

// ---------------- scan phase 1: per-block exclusive scan of ecnt ----------------
__global__ __launch_bounds__(SCAN_B) void k_scan1() {
    __shared__ int sh[SCAN_B];
    int b = blockIdx.x, t = threadIdx.x;
    int i = b * SCAN_B + t;
    int v = (i < N_NODES) ? g_ecnt[i] : 0;
    sh[t] = v;
    __syncthreads();
    for (int s = 1; s < SCAN_B; s <<= 1) {
        int x = (t >= s) ? sh[t - s] : 0;
        __syncthreads();
        sh[t] += x;
        __syncthreads();
    }
    if (i < N_NODES) g_off[i] = sh[t] - v;   // exclusive
    if (t == SCAN_B - 1) g_bsum[b] = sh[t];
}

// ---------------- scan phase 2 ----------------
__global__ void k_scan2() {
    if (threadIdx.x == 0) {
        int a = 0;
        for (int i = 0; i < NBLK; i++) { g_bo[i] = a; a += g_bsum[i]; }
    }
}

// ---------------- final offsets + cursors ----------------
__global__ void k_cursor() {
    int i  = blockIdx.x * blockDim.x + threadIdx.x;
    int st = gridDim.x * blockDim.x;
    for (int n = i; n < N_NODES; n += st) {
        int base = g_off[n] + g_bo[n >> 10];
        g_rowstart[n] = base;
        g_cursor[n]   = base;
    }
}

// ---------------- bucket fill ----------------
__global__ void k_bucket() {
    int i  = blockIdx.x * blockDim.x + threadIdx.x;
    int st = gridDim.x * blockDim.x;
    for (int e = i; e < N_EDGES; e += st) {
        int d = g_dst[e];
        int pos = atomicAdd(&g_cursor[d], 1);
        g_esrc[pos] = g_src[e];
    }
}

// ---------------- tf32 helpers ----------------
__device__ __forceinline__ unsigned f2tf32(float f) {
    unsigned u;
    asm("cvt.rna.tf32.f32 %0, %1;" : "=r"(u) : "f"(f));
    return u;
}

__device__ __forceinline__ void mma_tf32(float& c0, float& c1, float& c2, float& c3,
                                         unsigned a0, unsigned a1, unsigned a2, unsigned a3,
                                         unsigned b0, unsigned b1) {
    asm volatile(
        "mma.sync.aligned.m16n8k8.row.col.f32.tf32.tf32.f32 "
        "{%0,%1,%2,%3}, {%4,%5,%6,%7}, {%8,%9}, {%0,%1,%2,%3};"
        : "+f"(c0), "+f"(c1), "+f"(c2), "+f"(c3)
        : "r"(a0), "r"(a1), "r"(a2), "r"(a3), "r"(b0), "r"(b1));
}

// ---------------- GEMM: bufA = (A @ W) * dis[row]  (tf32, N-split for occupancy) ----------------
// Grid (391, 2). Block = 128 rows x 64 cols; 4 warps, warp = 32 rows (two m16 tiles).
// Smem: pre-packed B frags for this block's 64-col half: Bf[kc][nt][lane] =
// uint2{ tf32(W[kc*8+t][cb+nt*8+g]), tf32(W[kc*8+t+4][cb+nt*8+g]) }, lane = g*4+t.
// One lane-linear LDS.64 feeds TWO MMAs (MMA:LDS = 2:1). 64 acc regs/thread ->
// ~100 regs total -> 5 blocks/SM = 20 warps (2x R9 occupancy). A loads are clamped
// (branchless); A frags for kc+1 prefetched before the nt loop.
// Ain==nullptr -> read g_bufB (device-side symbol; host can't pass __device__ arrays).
__global__ __launch_bounds__(128) void k_gemm(const float* Ain,
                                              const float* __restrict__ W) {
    __shared__ uint2 Bf[16 * 8 * 32];   // 32768 B
    const float* A = Ain ? Ain : g_bufB;
    const int tid  = threadIdx.x;
    const int w    = tid >> 5;
    const int lane = tid & 31;
    const int g    = lane >> 2;   // fragment row group 0..7
    const int t    = lane & 3;    // thread-in-group 0..3
    const int cb   = blockIdx.y * 64;   // column base of this half

    // stage pre-packed B fragments (32 uint2 per thread)
    for (int idx = tid; idx < 16 * 8 * 32; idx += 128) {
        int l  = idx & 31;
        int nt = (idx >> 5) & 7;
        int kc = idx >> 8;
        int gg = l >> 2, tt = l & 3;
        int n  = cb + nt * 8 + gg;
        int k0 = kc * 8 + tt;
        uint2 b;
        b.x = f2tf32(W[(size_t)k0 * DIM + n]);
        b.y = f2tf32(W[(size_t)(k0 + 4) * DIM + n]);
        Bf[idx] = b;
    }
    __syncthreads();

    // rows handled by this thread: tile0 -> r0, r0+8 ; tile1 -> r0+16, r0+24
    const int rbase = blockIdx.x * 128 + w * 32;
    const int r0 = rbase + g;
    const int r1 = rbase + g + 8;
    const int r2 = rbase + g + 16;
    const int r3 = rbase + g + 24;
    const bool ok0 = r0 < N_NODES, ok1 = r1 < N_NODES;
    const bool ok2 = r2 < N_NODES, ok3 = r3 < N_NODES;
    // clamped pointers: out-of-range rows read row N-1 (valid data, never stored)
    const float* p0 = A + (size_t)(ok0 ? r0 : N_NODES - 1) * DIM;
    const float* p1 = A + (size_t)(ok1 ? r1 : N_NODES - 1) * DIM;
    const float* p2 = A + (size_t)(ok2 ? r2 : N_NODES - 1) * DIM;
    const float* p3 = A + (size_t)(ok3 ? r3 : N_NODES - 1) * DIM;

    float acc[2][8][4];
#pragma unroll
    for (int ti = 0; ti < 2; ti++)
#pragma unroll
        for (int nt = 0; nt < 8; nt++)
#pragma unroll
            for (int j = 0; j < 4; j++) acc[ti][nt][j] = 0.0f;

    // prefetch kc=0 A fragments
    unsigned a[8];
    a[0] = f2tf32(p0[t]);     a[1] = f2tf32(p1[t]);
    a[2] = f2tf32(p0[t + 4]); a[3] = f2tf32(p1[t + 4]);
    a[4] = f2tf32(p2[t]);     a[5] = f2tf32(p3[t]);
    a[6] = f2tf32(p2[t + 4]); a[7] = f2tf32(p3[t + 4]);

#pragma unroll
    for (int kc = 0; kc < 16; kc++) {
        unsigned an[8];
        if (kc < 15) {
            const int K1 = (kc + 1) * 8;
            an[0] = f2tf32(p0[K1 + t]);     an[1] = f2tf32(p1[K1 + t]);
            an[2] = f2tf32(p0[K1 + t + 4]); an[3] = f2tf32(p1[K1 + t + 4]);
            an[4] = f2tf32(p2[K1 + t]);     an[5] = f2tf32(p3[K1 + t]);
            an[6] = f2tf32(p2[K1 + t + 4]); an[7] = f2tf32(p3[K1 + t + 4]);
        }
#pragma unroll
        for (int nt = 0; nt < 8; nt++) {
            uint2 b = Bf[(kc * 8 + nt) * 32 + lane];  // LDS.64 conflict-free
            mma_tf32(acc[0][nt][0], acc[0][nt][1], acc[0][nt][2], acc[0][nt][3],
                     a[0], a[1], a[2], a[3], b.x, b.y);
            mma_tf32(acc[1][nt][0], acc[1][nt][1], acc[1][nt][2], acc[1][nt][3],
                     a[4], a[5], a[6], a[7], b.x, b.y);
        }
#pragma unroll
        for (int j = 0; j < 8; j++) a[j] = an[j];
    }

    // epilogue: scale by dis = rsqrt(deg), deg = ecnt + 1; cols {2t, 2t+1} per nt
    float d0 = ok0 ? rsqrtf((float)(g_ecnt[r0] + 1)) : 0.0f;
    float d1 = ok1 ? rsqrtf((float)(g_ecnt[r1] + 1)) : 0.0f;
    float d2 = ok2 ? rsqrtf((float)(g_ecnt[r2] + 1)) : 0.0f;
    float d3 = ok3 ? rsqrtf((float)(g_ecnt[r3] + 1)) : 0.0f;
#pragma unroll
    for (int nt = 0; nt < 8; nt++) {
        int col = cb + nt * 8 + 2 * t;
        if (ok0) *(float2*)&g_bufA[(size_t)r0 * DIM + col] =
            make_float2(acc[0][nt][0] * d0, acc[0][nt][1] * d0);
        if (ok1) *(float2*)&g_bufA[(size_t)r1 * DIM + col] =
            make_float2(acc[0][nt][2] * d1, acc[0][nt][3] * d1);
        if (ok2) *(float2*)&g_bufA[(size_t)r2 * DIM + col] =
            make_float2(acc[1][nt][0] * d2, acc[1][nt][1] * d2);
        if (ok3) *(float2*)&g_bufA[(size_t)r3 * DIM + col] =
            make_float2(acc[1][nt][2] * d3, acc[1][nt][3] * d3);
    }
}

// ---------------- RED.v4 helper ----------------
__device__ __forceinline__ void red_add_v4(float* p, float4 v) {
    unsigned long long gp = (unsigned long long)__cvta_generic_to_global(p);
    asm volatile("red.global.add.v4.f32 [%0], {%1,%2,%3,%4};"
                 :: "l"(gp), "f"(v.x), "f"(v.y), "f"(v.z), "f"(v.w)
                 : "memory");
}

// ---------------- aggregation: warp per node, CSR gather ----------------
template <bool POOL>
__global__ __launch_bounds__(256) void k_agg(const float* __restrict__ bias) {
    int gtid = blockIdx.x * blockDim.x + threadIdx.x;
    int warp = gtid >> 5;
    int lane = gtid & 31;
    int nw   = (gridDim.x * blockDim.x) >> 5;
    float4 b = *(const float4*)&bias[lane * 4];

    for (int n = warp; n < N_NODES; n += nw) {
        int start = g_rowstart[n];
        int cnt   = g_ecnt[n];
        float4 acc = *(const float4*)&g_bufA[(size_t)n * DIM + lane * 4];  // self loop

        int k = 0;
        for (; k + 8 <= cnt; k += 8) {
            int s0 = g_esrc[start + k + 0];
            int s1 = g_esrc[start + k + 1];
            int s2 = g_esrc[start + k + 2];
            int s3 = g_esrc[start + k + 3];
            int s4 = g_esrc[start + k + 4];
            int s5 = g_esrc[start + k + 5];
            int s6 = g_esrc[start + k + 6];
            int s7 = g_esrc[start + k + 7];
            float4 v0 = *(const float4*)&g_bufA[(size_t)s0 * DIM + lane * 4];
            float4 v1 = *(const float4*)&g_bufA[(size_t)s1 * DIM + lane * 4];
            float4 v2 = *(const float4*)&g_bufA[(size_t)s2 * DIM + lane * 4];
            float4 v3 = *(const float4*)&g_bufA[(size_t)s3 * DIM + lane * 4];
            float4 v4 = *(const float4*)&g_bufA[(size_t)s4 * DIM + lane * 4];
            float4 v5 = *(const float4*)&g_bufA[(size_t)s5 * DIM + lane * 4];
            float4 v6 = *(const float4*)&g_bufA[(size_t)s6 * DIM + lane * 4];
            float4 v7 = *(const float4*)&g_bufA[(size_t)s7 * DIM + lane * 4];
            acc.x += (v0.x + v1.x) + (v2.x + v3.x) + ((v4.x + v5.x) + (v6.x + v7.x));
            acc.y += (v0.y + v1.y) + (v2.y + v3.y) + ((v4.y + v5.y) + (v6.y + v7.y));
            acc.z += (v0.z + v1.z) + (v2.z + v3.z) + ((v4.z + v5.z) + (v6.z + v7.z));
            acc.w += (v0.w + v1.w) + (v2.w + v3.w) + ((v4.w + v5.w) + (v6.w + v7.w));
        }
        for (; k < cnt; k++) {
            int s = g_esrc[start + k];
            float4 v = *(const float4*)&g_bufA[(size_t)s * DIM + lane * 4];
            acc.x += v.x; acc.y += v.y; acc.z += v.z; acc.w += v.w;
        }

        float di = rsqrtf((float)(cnt + 1));
        float4 o;
        o.x = fmaxf(fmaf(acc.x, di, b.x), 0.0f);
        o.y = fmaxf(fmaf(acc.y, di, b.y), 0.0f);
        o.z = fmaxf(fmaf(acc.z, di, b.z), 0.0f);
        o.w = fmaxf(fmaf(acc.w, di, b.w), 0.0f);
        *(float4*)&g_bufB[(size_t)n * DIM + lane * 4] = o;

        if (POOL) {
            int g = g_batch[n];
            red_add_v4(&g_sums[g * DIM + lane * 4], o);
        }
    }
}

// ---------------- final FC ----------------
__global__ void k_final(const float* __restrict__ Wfc, const float* __restrict__ bfc,
                        float* __restrict__ out) {
    int idx = blockIdx.x * blockDim.x + threadIdx.x;
    if (idx >= NG * OUTD) return;
    int g = idx / OUTD;
    int o = idx % OUTD;
    float inv = 1.0f / fmaxf(g_cnts[g], 1.0f);
    float acc = 0.0f;
#pragma unroll 8
    for (int h = 0; h < DIM; h++) acc += g_sums[g * DIM + h] * Wfc[h * OUTD + o];
    out[idx] = acc * inv + bfc[o];
}

// ---------------- launch ----------------
extern "C" void kernel_launch(void* const* d_in, const int* in_sizes, int n_in,
                              void* d_out, int out_size) {
    const float* x     = (const float*)d_in[0];
    const void*  ei    = d_in[1];
    const void*  batch = d_in[2];
    const float* W1    = (const float*)d_in[3];
    const float* b1    = (const float*)d_in[4];
    const float* W2    = (const float*)d_in[5];
    const float* b2    = (const float*)d_in[6];
    const float* Wfc   = (const float*)d_in[7];
    const float* bfc   = (const float*)d_in[8];
    float* out = (float*)d_out;

    const dim3 gemm_grid((N_NODES + 127) / 128, 2);   // (391, 2)

    // launch order puts k_gemm (layer 1) at the ncu-captured slot (#4)
    k_init<<<256, 256>>>(ei);                       // 1
    k_convert<<<1024, 256>>>(ei, batch);            // 2
    k_scan1<<<NBLK, SCAN_B>>>();                    // 3
    k_gemm<<<gemm_grid, 128>>>(x, W1);              // 4  <- profiled
    k_scan2<<<1, 32>>>();                           // 5
    k_cursor<<<196, 256>>>();                       // 6
    k_bucket<<<1024, 256>>>();                      // 7
    k_agg<false><<<2368, 256>>>(b1);                // 8
    k_gemm<<<gemm_grid, 128>>>(nullptr, W2);        // 9
    k_agg<true><<<2368, 256>>>(b2);                 // 10
    k_final<<<4, 256>>>(Wfc, bfc, out);             // 11
}

// round 14
// speedup vs baseline: 1.1797x; 1.1797x over previous
#include <cuda_runtime.h>
#include <cuda_fp16.h>
#include <cstdint>

#define N_NODES 50000
#define N_EDGES 800000
#define DIM     128
#define NG      64
#define OUTD    16
#define SCAN_B  1024
#define NBLK    ((N_NODES + SCAN_B - 1) / SCAN_B)   // 49
#define WPACK_N 8192                                 // 16 kc * 16 nt * 32 lanes

// ---------------- scratch (static device globals; no allocation) ----------------
__device__ __align__(16) int   g_src[N_EDGES];
__device__ __align__(16) int   g_dst[N_EDGES];
__device__ __align__(16) int   g_esrc[N_EDGES];     // bucketed-by-dst src list
__device__ __align__(16) int   g_batch[N_NODES];
__device__ __align__(16) int   g_ecnt[N_NODES];     // in-degree (edges only)
__device__ __align__(16) int   g_off[N_NODES];      // block-local exclusive scan
__device__ __align__(16) int   g_rowstart[N_NODES]; // final CSR row start
__device__ __align__(16) int   g_cursor[N_NODES];   // bucket-fill cursors
__device__ int   g_bsum[NBLK];
__device__ int   g_bo[NBLK];
__device__ __align__(16)  uint2  g_Wpack[2 * WPACK_N];            // packed tf32 B frags
__device__ __align__(128) __half g_bufAh[(size_t)N_NODES * DIM];  // h*dis fp16 (gather src)
__device__ __align__(128) float  g_bufB[(size_t)N_NODES * DIM];   // layer output f32
__device__ __align__(16) float g_sums[NG * DIM];
__device__ __align__(16) float g_cnts[NG];
__device__ int g_is64;

// ---------------- init + dtype detect ----------------
__global__ void k_init(const void* ei) {
    int i  = blockIdx.x * blockDim.x + threadIdx.x;
    if (i == 0) {
        const unsigned long long* p = (const unsigned long long*)ei;
        bool is64 = true;
        for (int j = 0; j < 8; j++)
            if (p[j] >= (unsigned long long)N_NODES) is64 = false;
        g_is64 = is64 ? 1 : 0;
    }
    int st = gridDim.x * blockDim.x;
    for (int n = i; n < N_NODES; n += st) g_ecnt[n] = 0;
    for (int n = i; n < NG * DIM; n += st) g_sums[n] = 0.0f;
    for (int n = i; n < NG; n += st) g_cnts[n] = 0.0f;
}

// ---------------- convert indices + degree histogram + graph counts ----------------
__global__ void k_convert(const void* ei, const void* batch) {
    int i  = blockIdx.x * blockDim.x + threadIdx.x;
    int st = gridDim.x * blockDim.x;
    const bool is64 = (g_is64 != 0);
    for (int e = i; e < N_EDGES; e += st) {
        int s, d;
        if (is64) {
            s = (int)((const long long*)ei)[e];
            d = (int)((const long long*)ei)[N_EDGES + e];
        } else {
            s = ((const int*)ei)[e];
            d = ((const int*)ei)[N_EDGES + e];
        }
        g_src[e] = s;
        g_dst[e] = d;
        atomicAdd(&g_ecnt[d], 1);
    }
    for (int n = i; n < N_NODES; n += st) {
        int b = is64 ? (int)((const long long*)batch)[n]
                     : ((const int*)batch)[n];
        g_batch[n] = b;
        atomicAdd(&g_cnts[b], 1.0f);
    }
}

// ---------------- tf32 helpers ----------------
__device__ __forceinline__ unsigned f2tf32(float f) {
    unsigned u;
    asm("cvt.rna.tf32.f32 %0, %1;" : "=r"(u) : "f"(f));
    return u;
}

__device__ __forceinline__ void mma_tf32(float& c0, float& c1, float& c2, float& c3,
                                         unsigned a0, unsigned a1, unsigned a2, unsigned a3,
                                         unsigned b0, unsigned b1) {
    asm volatile(
        "mma.sync.aligned.m16n8k8.row.col.f32.tf32.tf32.f32 "
        "{%0,%1,%2,%3}, {%4,%5,%6,%7}, {%8,%9}, {%0,%1,%2,%3};"
        : "+f"(c0), "+f"(c1), "+f"(c2), "+f"(c3)
        : "r"(a0), "r"(a1), "r"(a2), "r"(a3), "r"(b0), "r"(b1));
}

// ---------------- pre-pack both W matrices into mma B-fragment layout ----------------
// Wpack[sel][ (kc*16+nt)*32 + lane ] = uint2{ tf32(W[kc*8+t][nt*8+g]),
//                                             tf32(W[kc*8+t+4][nt*8+g]) }, lane = g*4+t
__global__ void k_packW(const float* __restrict__ W1, const float* __restrict__ W2) {
    int i  = blockIdx.x * blockDim.x + threadIdx.x;
    int st = gridDim.x * blockDim.x;
    for (; i < 2 * WPACK_N; i += st) {
        int sel  = i >> 13;
        int idx  = i & (WPACK_N - 1);
        const float* W = sel ? W2 : W1;
        int lane = idx & 31;
        int nt   = (idx >> 5) & 15;
        int kc   = idx >> 9;
        int g = lane >> 2, t = lane & 3;
        int n  = nt * 8 + g;
        int k0 = kc * 8 + t;
        uint2 b;
        b.x = f2tf32(W[(size_t)k0 * DIM + n]);
        b.y = f2tf32(W[(size_t)(k0 + 4) * DIM + n]);
        g_Wpack[i] = b;
    }
}

// ---------------- scan phase 1: per-block exclusive scan of ecnt ----------------
__global__ __launch_bounds__(SCAN_B) void k_scan1() {
    __shared__ int sh[SCAN_B];
    int b = blockIdx.x, t = threadIdx.x;
    int i = b * SCAN_B + t;
    int v = (i < N_NODES) ? g_ecnt[i] : 0;
    sh[t] = v;
    __syncthreads();
    for (int s = 1; s < SCAN_B; s <<= 1) {
        int x = (t >= s) ? sh[t - s] : 0;
        __syncthreads();
        sh[t] += x;
        __syncthreads();
    }
    if (i < N_NODES) g_off[i] = sh[t] - v;   // exclusive
    if (t == SCAN_B - 1) g_bsum[b] = sh[t];
}

// ---------------- scan phase 2 ----------------
__global__ void k_scan2() {
    if (threadIdx.x == 0) {
        int a = 0;
        for (int i = 0; i < NBLK; i++) { g_bo[i] = a; a += g_bsum[i]; }
    }
}

// ---------------- final offsets + cursors ----------------
__global__ void k_cursor() {
    int i  = blockIdx.x * blockDim.x + threadIdx.x;
    int st = gridDim.x * blockDim.x;
    for (int n = i; n < N_NODES; n += st) {
        int base = g_off[n] + g_bo[n >> 10];
        g_rowstart[n] = base;
        g_cursor[n]   = base;
    }
}

// ---------------- bucket fill ----------------
__global__ void k_bucket() {
    int i  = blockIdx.x * blockDim.x + threadIdx.x;
    int st = gridDim.x * blockDim.x;
    for (int e = i; e < N_EDGES; e += st) {
        int d = g_dst[e];
        int pos = atomicAdd(&g_cursor[d], 1);
        g_esrc[pos] = g_src[e];
    }
}

// ---------------- GEMM: bufAh = fp16((A @ W) * dis[row])  (tf32, smem-staged A) ----------------
// 256 threads / 8 warps; block = 128 rows x 128 cols; warp = 16 rows (one m16 tile).
// B: pre-packed frags copied coalesced from g_Wpack (LDS.64 lane-linear, conflict-free).
// A: double-buffered smem chunks of 16 k (stride-20 rows -> conflict-free frag LDS).
// Ain==nullptr -> read g_bufB (device-side symbol; host can't pass __device__ arrays).
#define A_STRIDE 20
#define A_BUF    (128 * A_STRIDE)
__global__ __launch_bounds__(256) void k_gemm(const float* Ain, int wsel) {
    extern __shared__ char smem[];
    uint2* Bf = (uint2*)smem;                       // 64 KB
    float* As = (float*)(smem + WPACK_N * 8);       // 2 * 128*20*4 = 20480 B
    const float* A = Ain ? Ain : g_bufB;
    const int tid  = threadIdx.x;
    const int w    = tid >> 5;
    const int lane = tid & 31;
    const int g    = lane >> 2;
    const int t    = lane & 3;

    // stage packed B fragments (fully coalesced copy)
    {
        const uint2* Wp = g_Wpack + wsel * WPACK_N;
#pragma unroll
        for (int i = 0; i < WPACK_N / 256; i++)
            Bf[tid + i * 256] = Wp[tid + i * 256];
    }

    const int rbase = blockIdx.x * 128;
    const int r0 = rbase + w * 16 + g;
    const int r1 = r0 + 8;
    const bool ok0 = r0 < N_NODES, ok1 = r1 < N_NODES;

    // A staging: thread -> (row = tid>>1, koff = (tid&1)*8), 8 consecutive floats
    const int srow  = tid >> 1;
    const int skoff = (tid & 1) * 8;
    const float* srcRow = A + (size_t)min(rbase + srow, N_NODES - 1) * DIM;

    // prologue: chunk 0
    {
        float4 f0 = *(const float4*)&srcRow[skoff];
        float4 f1 = *(const float4*)&srcRow[skoff + 4];
        float* d = &As[srow * A_STRIDE + skoff];
        d[0] = f0.x; d[1] = f0.y; d[2] = f0.z; d[3] = f0.w;
        d[4] = f1.x; d[5] = f1.y; d[6] = f1.z; d[7] = f1.w;
    }
    __syncthreads();

    float acc[16][4];
#pragma unroll
    for (int nt = 0; nt < 16; nt++)
#pragma unroll
        for (int j = 0; j < 4; j++) acc[nt][j] = 0.0f;

    const int ra = w * 16 + g;       // local row of m16 tile (upper half)
    for (int c = 0; c < 8; c++) {
        float4 n0, n1;
        if (c < 7) {
            n0 = *(const float4*)&srcRow[(c + 1) * 16 + skoff];
            n1 = *(const float4*)&srcRow[(c + 1) * 16 + skoff + 4];
        }
        const float* Ab = &As[(c & 1) * A_BUF];
#pragma unroll
        for (int kc2 = 0; kc2 < 2; kc2++) {
            const int kl = kc2 * 8;
            unsigned a0 = f2tf32(Ab[ra * A_STRIDE + kl + t]);
            unsigned a1 = f2tf32(Ab[(ra + 8) * A_STRIDE + kl + t]);
            unsigned a2 = f2tf32(Ab[ra * A_STRIDE + kl + t + 4]);
            unsigned a3 = f2tf32(Ab[(ra + 8) * A_STRIDE + kl + t + 4]);
            const int kc = c * 2 + kc2;
#pragma unroll
            for (int nt = 0; nt < 16; nt++) {
                uint2 b = Bf[(kc * 16 + nt) * 32 + lane];  // LDS.64 conflict-free
                mma_tf32(acc[nt][0], acc[nt][1], acc[nt][2], acc[nt][3],
                         a0, a1, a2, a3, b.x, b.y);
            }
        }
        if (c < 7) {   // fill other buffer (safe: last read of it ended at prev sync)
            float* d = &As[((c + 1) & 1) * A_BUF + srow * A_STRIDE + skoff];
            d[0] = n0.x; d[1] = n0.y; d[2] = n0.z; d[3] = n0.w;
            d[4] = n1.x; d[5] = n1.y; d[6] = n1.z; d[7] = n1.w;
        }
        __syncthreads();
    }

    // epilogue: scale by dis = rsqrt(ecnt+1), store fp16
    float d0 = ok0 ? rsqrtf((float)(g_ecnt[r0] + 1)) : 0.0f;
    float d1 = ok1 ? rsqrtf((float)(g_ecnt[r1] + 1)) : 0.0f;
#pragma unroll
    for (int nt = 0; nt < 16; nt++) {
        int col = nt * 8 + 2 * t;
        if (ok0) *(__half2*)&g_bufAh[(size_t)r0 * DIM + col] =
            __floats2half2_rn(acc[nt][0] * d0, acc[nt][1] * d0);
        if (ok1) *(__half2*)&g_bufAh[(size_t)r1 * DIM + col] =
            __floats2half2_rn(acc[nt][2] * d1, acc[nt][3] * d1);
    }
}

// ---------------- helpers ----------------
__device__ __forceinline__ void red_add_v4(float* p, float4 v) {
    unsigned long long gp = (unsigned long long)__cvta_generic_to_global(p);
    asm volatile("red.global.add.v4.f32 [%0], {%1,%2,%3,%4};"
                 :: "l"(gp), "f"(v.x), "f"(v.y), "f"(v.z), "f"(v.w)
                 : "memory");
}

__device__ __forceinline__ float4 ldh4(const __half* p) {
    uint2 u = *(const uint2*)p;    // 4 halves, one 8B load
    __half2 h0 = *reinterpret_cast<__half2*>(&u.x);
    __half2 h1 = *reinterpret_cast<__half2*>(&u.y);
    float2 f0 = __half22float2(h0);
    float2 f1 = __half22float2(h1);
    return make_float4(f0.x, f0.y, f1.x, f1.y);
}

// ---------------- aggregation: warp per node, CSR gather (fp16 source) ----------------
// bufB[n] = relu(dis[n] * (bufAh[n] + sum_{s} bufAh[s]) + bias); POOL: RED into sums.
template <bool POOL>
__global__ __launch_bounds__(256) void k_agg(const float* __restrict__ bias) {
    int gtid = blockIdx.x * blockDim.x + threadIdx.x;
    int warp = gtid >> 5;
    int lane = gtid & 31;
    int nw   = (gridDim.x * blockDim.x) >> 5;
    float4 b = *(const float4*)&bias[lane * 4];
    const int fo = lane * 4;   // feature offset

    for (int n = warp; n < N_NODES; n += nw) {
        int start = g_rowstart[n];
        int cnt   = g_ecnt[n];
        float4 acc = ldh4(&g_bufAh[(size_t)n * DIM + fo]);  // self loop

        int k = 0;
        for (; k + 8 <= cnt; k += 8) {
            int s0 = g_esrc[start + k + 0];
            int s1 = g_esrc[start + k + 1];
            int s2 = g_esrc[start + k + 2];
            int s3 = g_esrc[start + k + 3];
            int s4 = g_esrc[start + k + 4];
            int s5 = g_esrc[start + k + 5];
            int s6 = g_esrc[start + k + 6];
            int s7 = g_esrc[start + k + 7];
            float4 v0 = ldh4(&g_bufAh[(size_t)s0 * DIM + fo]);
            float4 v1 = ldh4(&g_bufAh[(size_t)s1 * DIM + fo]);
            float4 v2 = ldh4(&g_bufAh[(size_t)s2 * DIM + fo]);
            float4 v3 = ldh4(&g_bufAh[(size_t)s3 * DIM + fo]);
            float4 v4 = ldh4(&g_bufAh[(size_t)s4 * DIM + fo]);
            float4 v5 = ldh4(&g_bufAh[(size_t)s5 * DIM + fo]);
            float4 v6 = ldh4(&g_bufAh[(size_t)s6 * DIM + fo]);
            float4 v7 = ldh4(&g_bufAh[(size_t)s7 * DIM + fo]);
            acc.x += (v0.x + v1.x) + (v2.x + v3.x) + ((v4.x + v5.x) + (v6.x + v7.x));
            acc.y += (v0.y + v1.y) + (v2.y + v3.y) + ((v4.y + v5.y) + (v6.y + v7.y));
            acc.z += (v0.z + v1.z) + (v2.z + v3.z) + ((v4.z + v5.z) + (v6.z + v7.z));
            acc.w += (v0.w + v1.w) + (v2.w + v3.w) + ((v4.w + v5.w) + (v6.w + v7.w));
        }
        for (; k < cnt; k++) {
            int s = g_esrc[start + k];
            float4 v = ldh4(&g_bufAh[(size_t)s * DIM + fo]);
            acc.x += v.x; acc.y += v.y; acc.z += v.z; acc.w += v.w;
        }

        float di = rsqrtf((float)(cnt + 1));
        float4 o;
        o.x = fmaxf(fmaf(acc.x, di, b.x), 0.0f);
        o.y = fmaxf(fmaf(acc.y, di, b.y), 0.0f);
        o.z = fmaxf(fmaf(acc.z, di, b.z), 0.0f);
        o.w = fmaxf(fmaf(acc.w, di, b.w), 0.0f);
        *(float4*)&g_bufB[(size_t)n * DIM + fo] = o;

        if (POOL) {
            int g = g_batch[n];
            red_add_v4(&g_sums[g * DIM + fo], o);
        }
    }
}

// ---------------- final FC ----------------
__global__ void k_final(const float* __restrict__ Wfc, const float* __restrict__ bfc,
                        float* __restrict__ out) {
    int idx = blockIdx.x * blockDim.x + threadIdx.x;
    if (idx >= NG * OUTD) return;
    int g = idx / OUTD;
    int o = idx % OUTD;
    float inv = 1.0f / fmaxf(g_cnts[g], 1.0f);
    float acc = 0.0f;
#pragma unroll 8
    for (int h = 0; h < DIM; h++) acc += g_sums[g * DIM + h] * Wfc[h * OUTD + o];
    out[idx] = acc * inv + bfc[o];
}

// ---------------- launch ----------------
extern "C" void kernel_launch(void* const* d_in, const int* in_sizes, int n_in,
                              void* d_out, int out_size) {
    const float* x     = (const float*)d_in[0];
    const void*  ei    = d_in[1];
    const void*  batch = d_in[2];
    const float* W1    = (const float*)d_in[3];
    const float* b1    = (const float*)d_in[4];
    const float* W2    = (const float*)d_in[5];
    const float* b2    = (const float*)d_in[6];
    const float* Wfc   = (const float*)d_in[7];
    const float* bfc   = (const float*)d_in[8];
    float* out = (float*)d_out;

    const int gemm_blocks = (N_NODES + 127) / 128;        // 391
    const int gemm_smem   = WPACK_N * 8 + 2 * A_BUF * 4;  // 65536 + 20480 = 86016 B

    // unconditional (no static guard -- harness rule): idempotent, not a stream op
    cudaFuncSetAttribute(k_gemm, cudaFuncAttributeMaxDynamicSharedMemorySize, gemm_smem);

    // launch order puts k_gemm (layer 1) at the ncu-captured slot (#4)
    k_init<<<256, 256>>>(ei);                         // 1
    k_convert<<<1024, 256>>>(ei, batch);              // 2
    k_packW<<<64, 256>>>(W1, W2);                     // 3
    k_gemm<<<gemm_blocks, 256, gemm_smem>>>(x, 0);    // 4  <- profiled
    k_scan1<<<NBLK, SCAN_B>>>();                      // 5
    k_scan2<<<1, 32>>>();                             // 6
    k_cursor<<<196, 256>>>();                         // 7
    k_bucket<<<1024, 256>>>();                        // 8
    k_agg<false><<<2368, 256>>>(b1);                  // 9
    k_gemm<<<gemm_blocks, 256, gemm_smem>>>(nullptr, 1);  // 10
    k_agg<true><<<2368, 256>>>(b2);                   // 11
    k_final<<<4, 256>>>(Wfc, bfc, out);               // 12
}

// round 15
// speedup vs baseline: 1.2307x; 1.0432x over previous
#include <cuda_runtime.h>
#include <cuda_fp16.h>
#include <cstdint>

#define N_NODES 50000
#define N_EDGES 800000
#define DIM     128
#define NG      64
#define OUTD    16
#define SCAN_B  1024
#define NBLK    ((N_NODES + SCAN_B - 1) / SCAN_B)   // 49
#define WPACK_N 8192                                 // 16 kc * 16 nt * 32 lanes

// ---------------- scratch (static device globals; no allocation) ----------------
__device__ __align__(16) int   g_src[N_EDGES];
__device__ __align__(16) int   g_dst[N_EDGES];
__device__ __align__(16) int   g_esrc[N_EDGES];     // bucketed-by-dst src list
__device__ __align__(16) int   g_batch[N_NODES];
__device__ __align__(16) int   g_ecnt[N_NODES];     // in-degree (edges only)
__device__ __align__(16) int   g_off[N_NODES];      // block-local exclusive scan
__device__ __align__(16) int   g_rowstart[N_NODES]; // final CSR row start
__device__ __align__(16) int   g_cursor[N_NODES];   // bucket-fill cursors
__device__ int   g_bsum[NBLK];
__device__ int   g_bo[NBLK];
__device__ __align__(16)  uint2  g_Wpack[2 * WPACK_N];            // packed tf32 B frags
__device__ __align__(128) __half g_bufAh[(size_t)N_NODES * DIM];  // h*dis fp16 (gather src)
__device__ __align__(128) float  g_bufB[(size_t)N_NODES * DIM];   // layer output f32
__device__ __align__(16) float g_sums[NG * DIM];
__device__ __align__(16) float g_cnts[NG];
__device__ int g_is64;

// ---------------- tf32 helpers ----------------
__device__ __forceinline__ unsigned f2tf32(float f) {
    unsigned u;
    asm("cvt.rna.tf32.f32 %0, %1;" : "=r"(u) : "f"(f));
    return u;
}

__device__ __forceinline__ void mma_tf32(float& c0, float& c1, float& c2, float& c3,
                                         unsigned a0, unsigned a1, unsigned a2, unsigned a3,
                                         unsigned b0, unsigned b1) {
    asm volatile(
        "mma.sync.aligned.m16n8k8.row.col.f32.tf32.tf32.f32 "
        "{%0,%1,%2,%3}, {%4,%5,%6,%7}, {%8,%9}, {%0,%1,%2,%3};"
        : "+f"(c0), "+f"(c1), "+f"(c2), "+f"(c3)
        : "r"(a0), "r"(a1), "r"(a2), "r"(a3), "r"(b0), "r"(b1));
}

// ---------------- prep: dtype detect + zero counters + pack both W matrices ----------------
// Wpack[sel][ (kc*16+nt)*32 + lane ] = uint2{ tf32(W[kc*8+t][nt*8+g]),
//                                             tf32(W[kc*8+t+4][nt*8+g]) }, lane = g*4+t
__global__ void k_prep(const void* ei, const float* __restrict__ W1,
                       const float* __restrict__ W2) {
    int i  = blockIdx.x * blockDim.x + threadIdx.x;
    int st = gridDim.x * blockDim.x;
    if (i == 0) {
        const unsigned long long* p = (const unsigned long long*)ei;
        bool is64 = true;
        for (int j = 0; j < 8; j++)
            if (p[j] >= (unsigned long long)N_NODES) is64 = false;
        g_is64 = is64 ? 1 : 0;
    }
    for (int n = i; n < N_NODES; n += st) g_ecnt[n] = 0;
    for (int n = i; n < NG * DIM; n += st) g_sums[n] = 0.0f;
    for (int n = i; n < NG; n += st) g_cnts[n] = 0.0f;
    for (int j = i; j < 2 * WPACK_N; j += st) {
        int sel  = j >> 13;
        int idx  = j & (WPACK_N - 1);
        const float* W = sel ? W2 : W1;
        int lane = idx & 31;
        int nt   = (idx >> 5) & 15;
        int kc   = idx >> 9;
        int g = lane >> 2, t = lane & 3;
        int n  = nt * 8 + g;
        int k0 = kc * 8 + t;
        uint2 b;
        b.x = f2tf32(W[(size_t)k0 * DIM + n]);
        b.y = f2tf32(W[(size_t)(k0 + 4) * DIM + n]);
        g_Wpack[j] = b;
    }
}

// ---------------- convert indices + degree histogram + graph counts ----------------
__global__ void k_convert(const void* ei, const void* batch) {
    int i  = blockIdx.x * blockDim.x + threadIdx.x;
    int st = gridDim.x * blockDim.x;
    const bool is64 = (g_is64 != 0);
    for (int e = i; e < N_EDGES; e += st) {
        int s, d;
        if (is64) {
            s = (int)((const long long*)ei)[e];
            d = (int)((const long long*)ei)[N_EDGES + e];
        } else {
            s = ((const int*)ei)[e];
            d = ((const int*)ei)[N_EDGES + e];
        }
        g_src[e] = s;
        g_dst[e] = d;
        atomicAdd(&g_ecnt[d], 1);
    }
    for (int n = i; n < N_NODES; n += st) {
        int b = is64 ? (int)((const long long*)batch)[n]
                     : ((const int*)batch)[n];
        g_batch[n] = b;
        atomicAdd(&g_cnts[b], 1.0f);
    }
}

// ---------------- scan phase 1: per-block exclusive scan of ecnt ----------------
__global__ __launch_bounds__(SCAN_B) void k_scan1() {
    __shared__ int sh[SCAN_B];
    int b = blockIdx.x, t = threadIdx.x;
    int i = b * SCAN_B + t;
    int v = (i < N_NODES) ? g_ecnt[i] : 0;
    sh[t] = v;
    __syncthreads();
    for (int s = 1; s < SCAN_B; s <<= 1) {
        int x = (t >= s) ? sh[t - s] : 0;
        __syncthreads();
        sh[t] += x;
        __syncthreads();
    }
    if (i < N_NODES) g_off[i] = sh[t] - v;   // exclusive
    if (t == SCAN_B - 1) g_bsum[b] = sh[t];
}

// ---------------- scan phase 2 ----------------
__global__ void k_scan2() {
    if (threadIdx.x == 0) {
        int a = 0;
        for (int i = 0; i < NBLK; i++) { g_bo[i] = a; a += g_bsum[i]; }
    }
}

// ---------------- final offsets + cursors ----------------
__global__ void k_cursor() {
    int i  = blockIdx.x * blockDim.x + threadIdx.x;
    int st = gridDim.x * blockDim.x;
    for (int n = i; n < N_NODES; n += st) {
        int base = g_off[n] + g_bo[n >> 10];
        g_rowstart[n] = base;
        g_cursor[n]   = base;
    }
}

// ---------------- bucket fill ----------------
__global__ void k_bucket() {
    int i  = blockIdx.x * blockDim.x + threadIdx.x;
    int st = gridDim.x * blockDim.x;
    for (int e = i; e < N_EDGES; e += st) {
        int d = g_dst[e];
        int pos = atomicAdd(&g_cursor[d], 1);
        g_esrc[pos] = g_src[e];
    }
}

// ---------------- GEMM: bufAh = fp16((A @ W) * dis[row])  (tf32, 2 row-tiles/block) ----------------
// 256 threads / 8 warps; block = 256 rows (two 128-row tiles) x 128 cols; warp = 16 rows.
// B frags staged ONCE per block (coalesced copy from g_Wpack), reused by both tiles.
// A: double-buffered smem chunks of 16 k (stride-20 rows -> conflict-free frag LDS).
// Ain==nullptr -> read g_bufB (device-side symbol; host can't pass __device__ arrays).
#define A_STRIDE 20
#define A_BUF    (128 * A_STRIDE)
__global__ __launch_bounds__(256) void k_gemm(const float* Ain, int wsel) {
    extern __shared__ char smem[];
    uint2* Bf = (uint2*)smem;                       // 64 KB
    float* As = (float*)(smem + WPACK_N * 8);       // 2 * 128*20*4 = 20480 B
    const float* A = Ain ? Ain : g_bufB;
    const int tid  = threadIdx.x;
    const int w    = tid >> 5;
    const int lane = tid & 31;
    const int g    = lane >> 2;
    const int t    = lane & 3;

    // stage packed B fragments once (fully coalesced copy); visible after first sync
    {
        const uint2* Wp = g_Wpack + wsel * WPACK_N;
#pragma unroll
        for (int i = 0; i < WPACK_N / 256; i++)
            Bf[tid + i * 256] = Wp[tid + i * 256];
    }

    const int srow  = tid >> 1;          // A staging: row in tile
    const int skoff = (tid & 1) * 8;     // 8 consecutive floats
    const int ra    = w * 16 + g;        // local row of m16 tile (upper half)

    for (int tile = 0; tile < 2; tile++) {
        const int rbase = blockIdx.x * 256 + tile * 128;
        const int r0 = rbase + ra;
        const int r1 = r0 + 8;
        const bool ok0 = r0 < N_NODES, ok1 = r1 < N_NODES;
        const float* srcRow = A + (size_t)min(rbase + srow, N_NODES - 1) * DIM;

        // prologue: chunk 0 -> buffer 0
        {
            float4 f0 = *(const float4*)&srcRow[skoff];
            float4 f1 = *(const float4*)&srcRow[skoff + 4];
            float* d = &As[srow * A_STRIDE + skoff];
            d[0] = f0.x; d[1] = f0.y; d[2] = f0.z; d[3] = f0.w;
            d[4] = f1.x; d[5] = f1.y; d[6] = f1.z; d[7] = f1.w;
        }
        __syncthreads();

        float acc[16][4];
#pragma unroll
        for (int nt = 0; nt < 16; nt++)
#pragma unroll
            for (int j = 0; j < 4; j++) acc[nt][j] = 0.0f;

        for (int c = 0; c < 8; c++) {
            float4 n0, n1;
            if (c < 7) {
                n0 = *(const float4*)&srcRow[(c + 1) * 16 + skoff];
                n1 = *(const float4*)&srcRow[(c + 1) * 16 + skoff + 4];
            }
            const float* Ab = &As[(c & 1) * A_BUF];
#pragma unroll
            for (int kc2 = 0; kc2 < 2; kc2++) {
                const int kl = kc2 * 8;
                unsigned a0 = f2tf32(Ab[ra * A_STRIDE + kl + t]);
                unsigned a1 = f2tf32(Ab[(ra + 8) * A_STRIDE + kl + t]);
                unsigned a2 = f2tf32(Ab[ra * A_STRIDE + kl + t + 4]);
                unsigned a3 = f2tf32(Ab[(ra + 8) * A_STRIDE + kl + t + 4]);
                const int kc = c * 2 + kc2;
#pragma unroll
                for (int nt = 0; nt < 16; nt++) {
                    uint2 b = Bf[(kc * 16 + nt) * 32 + lane];  // LDS.64 conflict-free
                    mma_tf32(acc[nt][0], acc[nt][1], acc[nt][2], acc[nt][3],
                             a0, a1, a2, a3, b.x, b.y);
                }
            }
            if (c < 7) {   // fill other buffer (its last reader finished at prev sync)
                float* d = &As[((c + 1) & 1) * A_BUF + srow * A_STRIDE + skoff];
                d[0] = n0.x; d[1] = n0.y; d[2] = n0.z; d[3] = n0.w;
                d[4] = n1.x; d[5] = n1.y; d[6] = n1.z; d[7] = n1.w;
            }
            __syncthreads();
        }

        // epilogue: scale by dis = rsqrt(ecnt+1), store fp16
        float d0 = ok0 ? rsqrtf((float)(g_ecnt[r0] + 1)) : 0.0f;
        float d1 = ok1 ? rsqrtf((float)(g_ecnt[r1] + 1)) : 0.0f;
#pragma unroll
        for (int nt = 0; nt < 16; nt++) {
            int col = nt * 8 + 2 * t;
            if (ok0) *(__half2*)&g_bufAh[(size_t)r0 * DIM + col] =
                __floats2half2_rn(acc[nt][0] * d0, acc[nt][1] * d0);
            if (ok1) *(__half2*)&g_bufAh[(size_t)r1 * DIM + col] =
                __floats2half2_rn(acc[nt][2] * d1, acc[nt][3] * d1);
        }
        __syncthreads();   // tile boundary: As reuse + Bf persistence
    }
}

// ---------------- helpers ----------------
__device__ __forceinline__ void red_add_v4(float* p, float4 v) {
    unsigned long long gp = (unsigned long long)__cvta_generic_to_global(p);
    asm volatile("red.global.add.v4.f32 [%0], {%1,%2,%3,%4};"
                 :: "l"(gp), "f"(v.x), "f"(v.y), "f"(v.z), "f"(v.w)
                 : "memory");
}

__device__ __forceinline__ float4 ldh4(const __half* p) {
    uint2 u = *(const uint2*)p;    // 4 halves, one 8B load
    __half2 h0 = *reinterpret_cast<__half2*>(&u.x);
    __half2 h1 = *reinterpret_cast<__half2*>(&u.y);
    float2 f0 = __half22float2(h0);
    float2 f1 = __half22float2(h1);
    return make_float4(f0.x, f0.y, f1.x, f1.y);
}

// ---------------- aggregation: warp per node, CSR gather (fp16 source) ----------------
// bufB[n] = relu(dis[n] * (bufAh[n] + sum_{s} bufAh[s]) + bias); POOL: RED into sums.
template <bool POOL>
__global__ __launch_bounds__(256) void k_agg(const float* __restrict__ bias) {
    int gtid = blockIdx.x * blockDim.x + threadIdx.x;
    int warp = gtid >> 5;
    int lane = gtid & 31;
    int nw   = (gridDim.x * blockDim.x) >> 5;
    float4 b = *(const float4*)&bias[lane * 4];
    const int fo = lane * 4;   // feature offset

    for (int n = warp; n < N_NODES; n += nw) {
        int start = g_rowstart[n];
        int cnt   = g_ecnt[n];
        float4 acc = ldh4(&g_bufAh[(size_t)n * DIM + fo]);  // self loop

        int k = 0;
        for (; k + 8 <= cnt; k += 8) {
            int s0 = g_esrc[start + k + 0];
            int s1 = g_esrc[start + k + 1];
            int s2 = g_esrc[start + k + 2];
            int s3 = g_esrc[start + k + 3];
            int s4 = g_esrc[start + k + 4];
            int s5 = g_esrc[start + k + 5];
            int s6 = g_esrc[start + k + 6];
            int s7 = g_esrc[start + k + 7];
            float4 v0 = ldh4(&g_bufAh[(size_t)s0 * DIM + fo]);
            float4 v1 = ldh4(&g_bufAh[(size_t)s1 * DIM + fo]);
            float4 v2 = ldh4(&g_bufAh[(size_t)s2 * DIM + fo]);
            float4 v3 = ldh4(&g_bufAh[(size_t)s3 * DIM + fo]);
            float4 v4 = ldh4(&g_bufAh[(size_t)s4 * DIM + fo]);
            float4 v5 = ldh4(&g_bufAh[(size_t)s5 * DIM + fo]);
            float4 v6 = ldh4(&g_bufAh[(size_t)s6 * DIM + fo]);
            float4 v7 = ldh4(&g_bufAh[(size_t)s7 * DIM + fo]);
            acc.x += (v0.x + v1.x) + (v2.x + v3.x) + ((v4.x + v5.x) + (v6.x + v7.x));
            acc.y += (v0.y + v1.y) + (v2.y + v3.y) + ((v4.y + v5.y) + (v6.y + v7.y));
            acc.z += (v0.z + v1.z) + (v2.z + v3.z) + ((v4.z + v5.z) + (v6.z + v7.z));
            acc.w += (v0.w + v1.w) + (v2.w + v3.w) + ((v4.w + v5.w) + (v6.w + v7.w));
        }
        for (; k < cnt; k++) {
            int s = g_esrc[start + k];
            float4 v = ldh4(&g_bufAh[(size_t)s * DIM + fo]);
            acc.x += v.x; acc.y += v.y; acc.z += v.z; acc.w += v.w;
        }

        float di = rsqrtf((float)(cnt + 1));
        float4 o;
        o.x = fmaxf(fmaf(acc.x, di, b.x), 0.0f);
        o.y = fmaxf(fmaf(acc.y, di, b.y), 0.0f);
        o.z = fmaxf(fmaf(acc.z, di, b.z), 0.0f);
        o.w = fmaxf(fmaf(acc.w, di, b.w), 0.0f);
        *(float4*)&g_bufB[(size_t)n * DIM + fo] = o;

        if (POOL) {
            int g = g_batch[n];
            red_add_v4(&g_sums[g * DIM + fo], o);
        }
    }
}

// ---------------- final FC ----------------
__global__ void k_final(const float* __restrict__ Wfc, const float* __restrict__ bfc,
                        float* __restrict__ out) {
    int idx = blockIdx.x * blockDim.x + threadIdx.x;
    if (idx >= NG * OUTD) return;
    int g = idx / OUTD;
    int o = idx % OUTD;
    float inv = 1.0f / fmaxf(g_cnts[g], 1.0f);
    float acc = 0.0f;
#pragma unroll 8
    for (int h = 0; h < DIM; h++) acc += g_sums[g * DIM + h] * Wfc[h * OUTD + o];
    out[idx] = acc * inv + bfc[o];
}

// ---------------- launch ----------------
extern "C" void kernel_launch(void* const* d_in, const int* in_sizes, int n_in,
                              void* d_out, int out_size) {
    const float* x     = (const float*)d_in[0];
    const void*  ei    = d_in[1];
    const void*  batch = d_in[2];
    const float* W1    = (const float*)d_in[3];
    const float* b1    = (const float*)d_in[4];
    const float* W2    = (const float*)d_in[5];
    const float* b2    = (const float*)d_in[6];
    const float* Wfc   = (const float*)d_in[7];
    const float* bfc   = (const float*)d_in[8];
    float* out = (float*)d_out;

    const int gemm_blocks = (N_NODES + 255) / 256;        // 196
    const int gemm_smem   = WPACK_N * 8 + 2 * A_BUF * 4;  // 86016 B

    // unconditional (no static guard -- harness rule): idempotent, not a stream op
    cudaFuncSetAttribute(k_gemm, cudaFuncAttributeMaxDynamicSharedMemorySize, gemm_smem);

    // fork-join: CSR build on side stream overlaps gemm1 on main stream.
    // Created per call, intentionally not destroyed while capture may be live
    // (kernel_launch runs only twice: correctness + capture; bounded leak).
    cudaStream_t s1;
    cudaStreamCreateWithFlags(&s1, cudaStreamNonBlocking);
    cudaEvent_t e1, e2;
    cudaEventCreateWithFlags(&e1, cudaEventDisableTiming);
    cudaEventCreateWithFlags(&e2, cudaEventDisableTiming);

    k_prep<<<64, 256>>>(ei, W1, W2);                    // 1: detect+zero+packW
    k_convert<<<1024, 256>>>(ei, batch);                // 2
    cudaEventRecord(e1, 0);
    cudaStreamWaitEvent(s1, e1, 0);
    k_scan1<<<NBLK, SCAN_B, 0, s1>>>();                 // 3 (side)
    k_gemm<<<gemm_blocks, 256, gemm_smem>>>(x, 0);      // 4 (main) <- profiled
    k_scan2<<<1, 32, 0, s1>>>();                        // 5 (side)
    k_cursor<<<196, 256, 0, s1>>>();                    // 6 (side)
    k_bucket<<<1024, 256, 0, s1>>>();                   // 7 (side)
    cudaEventRecord(e2, s1);
    cudaStreamWaitEvent(0, e2, 0);
    k_agg<false><<<2368, 256>>>(b1);                    // 8
    k_gemm<<<gemm_blocks, 256, gemm_smem>>>(nullptr, 1);// 9
    k_agg<true><<<2368, 256>>>(b2);                     // 10
    k_final<<<4, 256>>>(Wfc, bfc, out);                 // 11
}

// round 16
// speedup vs baseline: 1.2621x; 1.0255x over previous
#include <cuda_runtime.h>
#include <cuda_fp16.h>
#include <cstdint>

#define N_NODES 50000
#define N_EDGES 800000
#define DIM     128
#define NG      64
#define OUTD    16
#define SCAN_B  1024
#define NBLK    ((N_NODES + SCAN_B - 1) / SCAN_B)   // 49
#define WPACK_N 4096                                 // 8 kc16 * 16 nt * 32 lanes

// ---------------- scratch (static device globals; no allocation) ----------------
__device__ __align__(16) int   g_src[N_EDGES];
__device__ __align__(16) int   g_dst[N_EDGES];
__device__ __align__(16) int   g_esrc[N_EDGES];     // bucketed-by-dst src list
__device__ __align__(16) int   g_batch[N_NODES];
__device__ __align__(16) int   g_ecnt[N_NODES];     // in-degree (edges only)
__device__ __align__(16) int   g_off[N_NODES];      // block-local exclusive scan
__device__ __align__(16) int   g_rowstart[N_NODES]; // final CSR row start
__device__ __align__(16) int   g_cursor[N_NODES];   // bucket-fill cursors
__device__ int   g_bsum[NBLK];
__device__ int   g_bo[NBLK];
__device__ __align__(16)  uint2  g_Wpack[2 * WPACK_N];            // packed fp16 B frags
__device__ __align__(128) __half g_bufAh[(size_t)N_NODES * DIM];  // h*dis fp16 (gather src)
__device__ __align__(128) float  g_bufB[(size_t)N_NODES * DIM];   // layer output f32
__device__ __align__(16) float g_sums[NG * DIM];
__device__ __align__(16) float g_cnts[NG];
__device__ int g_is64;

// ---------------- fp16 mma helper ----------------
// m16n8k16, thread (g=lane>>2, t=lane&3):
//   a0={A[g][2t],A[g][2t+1]}  a1={A[g+8][2t],..}  a2={A[g][2t+8],..}  a3={A[g+8][2t+8],..}
//   b0={B[2t][n],B[2t+1][n]}  b1={B[2t+8][n],B[2t+9][n]}   (B row = k, n = nt*8+g)
//   c0,c1 = row g cols {2t,2t+1}; c2,c3 = row g+8
__device__ __forceinline__ void mma_f16(float& c0, float& c1, float& c2, float& c3,
                                        unsigned a0, unsigned a1, unsigned a2, unsigned a3,
                                        unsigned b0, unsigned b1) {
    asm volatile(
        "mma.sync.aligned.m16n8k16.row.col.f32.f16.f16.f32 "
        "{%0,%1,%2,%3}, {%4,%5,%6,%7}, {%8,%9}, {%0,%1,%2,%3};"
        : "+f"(c0), "+f"(c1), "+f"(c2), "+f"(c3)
        : "r"(a0), "r"(a1), "r"(a2), "r"(a3), "r"(b0), "r"(b1));
}

__device__ __forceinline__ unsigned pack_h2(float lo, float hi) {
    __half2 h = __floats2half2_rn(lo, hi);
    return *reinterpret_cast<unsigned*>(&h);
}

// ---------------- prep: dtype detect + zero counters + pack both W matrices (fp16 frags) ----------------
// Wpack[sel][(kc*16+nt)*32 + lane] = uint2{ h2(W[k0+2t][n],W[k0+2t+1][n]),
//                                           h2(W[k0+8+2t][n],W[k0+9+2t][n]) }, k0=kc*16, n=nt*8+g
__global__ void k_prep(const void* ei, const float* __restrict__ W1,
                       const float* __restrict__ W2) {
    int i  = blockIdx.x * blockDim.x + threadIdx.x;
    int st = gridDim.x * blockDim.x;
    if (i == 0) {
        const unsigned long long* p = (const unsigned long long*)ei;
        bool is64 = true;
        for (int j = 0; j < 8; j++)
            if (p[j] >= (unsigned long long)N_NODES) is64 = false;
        g_is64 = is64 ? 1 : 0;
    }
    for (int n = i; n < N_NODES; n += st) g_ecnt[n] = 0;
    for (int n = i; n < NG * DIM; n += st) g_sums[n] = 0.0f;
    for (int n = i; n < NG; n += st) g_cnts[n] = 0.0f;
    for (int j = i; j < 2 * WPACK_N; j += st) {
        int sel  = j >> 12;
        int idx  = j & (WPACK_N - 1);
        const float* W = sel ? W2 : W1;
        int lane = idx & 31;
        int nt   = (idx >> 5) & 15;
        int kc   = idx >> 9;            // 0..7
        int g = lane >> 2, t = lane & 3;
        int n  = nt * 8 + g;
        int k0 = kc * 16;
        uint2 b;
        b.x = pack_h2(W[(size_t)(k0 + 2 * t) * DIM + n],
                      W[(size_t)(k0 + 2 * t + 1) * DIM + n]);
        b.y = pack_h2(W[(size_t)(k0 + 8 + 2 * t) * DIM + n],
                      W[(size_t)(k0 + 9 + 2 * t) * DIM + n]);
        g_Wpack[j] = b;
    }
}

// ---------------- convert indices + degree histogram + graph counts ----------------
__global__ void k_convert(const void* ei, const void* batch) {
    int i  = blockIdx.x * blockDim.x + threadIdx.x;
    int st = gridDim.x * blockDim.x;
    const bool is64 = (g_is64 != 0);
    for (int e = i; e < N_EDGES; e += st) {
        int s, d;
        if (is64) {
            s = (int)((const long long*)ei)[e];
            d = (int)((const long long*)ei)[N_EDGES + e];
        } else {
            s = ((const int*)ei)[e];
            d = ((const int*)ei)[N_EDGES + e];
        }
        g_src[e] = s;
        g_dst[e] = d;
        atomicAdd(&g_ecnt[d], 1);
    }
    for (int n = i; n < N_NODES; n += st) {
        int b = is64 ? (int)((const long long*)batch)[n]
                     : ((const int*)batch)[n];
        g_batch[n] = b;
        atomicAdd(&g_cnts[b], 1.0f);
    }
}

// ---------------- scan phase 1: per-block exclusive scan of ecnt ----------------
__global__ __launch_bounds__(SCAN_B) void k_scan1() {
    __shared__ int sh[SCAN_B];
    int b = blockIdx.x, t = threadIdx.x;
    int i = b * SCAN_B + t;
    int v = (i < N_NODES) ? g_ecnt[i] : 0;
    sh[t] = v;
    __syncthreads();
    for (int s = 1; s < SCAN_B; s <<= 1) {
        int x = (t >= s) ? sh[t - s] : 0;
        __syncthreads();
        sh[t] += x;
        __syncthreads();
    }
    if (i < N_NODES) g_off[i] = sh[t] - v;   // exclusive
    if (t == SCAN_B - 1) g_bsum[b] = sh[t];
}

// ---------------- scan phase 2 ----------------
__global__ void k_scan2() {
    if (threadIdx.x == 0) {
        int a = 0;
        for (int i = 0; i < NBLK; i++) { g_bo[i] = a; a += g_bsum[i]; }
    }
}

// ---------------- final offsets + cursors ----------------
__global__ void k_cursor() {
    int i  = blockIdx.x * blockDim.x + threadIdx.x;
    int st = gridDim.x * blockDim.x;
    for (int n = i; n < N_NODES; n += st) {
        int base = g_off[n] + g_bo[n >> 10];
        g_rowstart[n] = base;
        g_cursor[n]   = base;
    }
}

// ---------------- bucket fill ----------------
__global__ void k_bucket() {
    int i  = blockIdx.x * blockDim.x + threadIdx.x;
    int st = gridDim.x * blockDim.x;
    for (int e = i; e < N_EDGES; e += st) {
        int d = g_dst[e];
        int pos = atomicAdd(&g_cursor[d], 1);
        g_esrc[pos] = g_src[e];
    }
}

// ---------------- GEMM: bufAh = fp16((A @ W) * dis[row])  (fp16 m16n8k16) ----------------
// 256 threads / 8 warps; block = 128 rows x 128 cols; warp = 16 rows (one m16 tile).
// B: pre-packed fp16 frags (32 KB) staged coalesced; one LDS.64 per (kc,nt), conflict-free.
// A: staged as fp16 per k16 chunk, double-buffered; row stride 12 words ->
//    frag LDS banks {12g+t} mod 32 all distinct (conflict-free).
// Ain==nullptr -> read g_bufB (device-side symbol; host can't pass __device__ arrays).
#define A_STRIDE_W 12                 // 32-bit words per row-chunk (8 data + 4 pad)
#define A_BUF_W    (128 * A_STRIDE_W) // 1536 words per buffer
__global__ __launch_bounds__(256) void k_gemm(const float* Ain, int wsel) {
    __shared__ uint2    Bf[WPACK_N];        // 32768 B
    __shared__ unsigned As[2 * A_BUF_W];    // 12288 B
    const float* A = Ain ? Ain : g_bufB;
    const int tid  = threadIdx.x;
    const int w    = tid >> 5;
    const int lane = tid & 31;
    const int g    = lane >> 2;
    const int t    = lane & 3;

    // stage packed B fragments once (fully coalesced copy); visible after first sync
    {
        const uint2* Wp = g_Wpack + wsel * WPACK_N;
#pragma unroll
        for (int i = 0; i < WPACK_N / 256; i++)
            Bf[tid + i * 256] = Wp[tid + i * 256];
    }

    const int rbase = blockIdx.x * 128;
    const int ra    = w * 16 + g;        // local row (upper half of m16 tile)
    const int r0 = rbase + ra;
    const int r1 = r0 + 8;
    const bool ok0 = r0 < N_NODES, ok1 = r1 < N_NODES;

    // A staging: thread -> (row = tid>>1, 8 floats at koff = (tid&1)*8) per k16 chunk
    const int srow  = tid >> 1;
    const int skoff = (tid & 1) * 8;
    const float* srcRow = A + (size_t)min(rbase + srow, N_NODES - 1) * DIM;
    unsigned* const myAs = &As[srow * A_STRIDE_W + (tid & 1) * 4];

    // prologue: chunk 0 -> buffer 0 (f32 -> fp16 at staging; one STS.128)
    {
        float4 f0 = *(const float4*)&srcRow[skoff];
        float4 f1 = *(const float4*)&srcRow[skoff + 4];
        uint4 pk;
        pk.x = pack_h2(f0.x, f0.y); pk.y = pack_h2(f0.z, f0.w);
        pk.z = pack_h2(f1.x, f1.y); pk.w = pack_h2(f1.z, f1.w);
        *(uint4*)myAs = pk;
    }
    __syncthreads();

    float acc[16][4];
#pragma unroll
    for (int nt = 0; nt < 16; nt++)
#pragma unroll
        for (int j = 0; j < 4; j++) acc[nt][j] = 0.0f;

    for (int c = 0; c < 8; c++) {
        float4 f0, f1;
        if (c < 7) {
            f0 = *(const float4*)&srcRow[(c + 1) * 16 + skoff];
            f1 = *(const float4*)&srcRow[(c + 1) * 16 + skoff + 4];
        }
        const unsigned* Ab = &As[(c & 1) * A_BUF_W];
        // A fragments: 4 conflict-free LDS.32 (each = half2)
        unsigned a0 = Ab[ra * A_STRIDE_W + t];
        unsigned a1 = Ab[(ra + 8) * A_STRIDE_W + t];
        unsigned a2 = Ab[ra * A_STRIDE_W + 4 + t];
        unsigned a3 = Ab[(ra + 8) * A_STRIDE_W + 4 + t];
#pragma unroll
        for (int nt = 0; nt < 16; nt++) {
            uint2 b = Bf[(c * 16 + nt) * 32 + lane];   // LDS.64 conflict-free
            mma_f16(acc[nt][0], acc[nt][1], acc[nt][2], acc[nt][3],
                    a0, a1, a2, a3, b.x, b.y);
        }
        if (c < 7) {   // fill other buffer (its last reader finished at prev sync)
            uint4 pk;
            pk.x = pack_h2(f0.x, f0.y); pk.y = pack_h2(f0.z, f0.w);
            pk.z = pack_h2(f1.x, f1.y); pk.w = pack_h2(f1.z, f1.w);
            *(uint4*)&As[((c + 1) & 1) * A_BUF_W + srow * A_STRIDE_W + (tid & 1) * 4] = pk;
        }
        __syncthreads();
    }

    // epilogue: scale by dis = rsqrt(ecnt+1), store fp16
    float d0 = ok0 ? rsqrtf((float)(g_ecnt[r0] + 1)) : 0.0f;
    float d1 = ok1 ? rsqrtf((float)(g_ecnt[r1] + 1)) : 0.0f;
#pragma unroll
    for (int nt = 0; nt < 16; nt++) {
        int col = nt * 8 + 2 * t;
        if (ok0) *(__half2*)&g_bufAh[(size_t)r0 * DIM + col] =
            __floats2half2_rn(acc[nt][0] * d0, acc[nt][1] * d0);
        if (ok1) *(__half2*)&g_bufAh[(size_t)r1 * DIM + col] =
            __floats2half2_rn(acc[nt][2] * d1, acc[nt][3] * d1);
    }
}

// ---------------- helpers ----------------
__device__ __forceinline__ void red_add_v4(float* p, float4 v) {
    unsigned long long gp = (unsigned long long)__cvta_generic_to_global(p);
    asm volatile("red.global.add.v4.f32 [%0], {%1,%2,%3,%4};"
                 :: "l"(gp), "f"(v.x), "f"(v.y), "f"(v.z), "f"(v.w)
                 : "memory");
}

__device__ __forceinline__ float4 ldh4(const __half* p) {
    uint2 u = *(const uint2*)p;    // 4 halves, one 8B load
    __half2 h0 = *reinterpret_cast<__half2*>(&u.x);
    __half2 h1 = *reinterpret_cast<__half2*>(&u.y);
    float2 f0 = __half22float2(h0);
    float2 f1 = __half22float2(h1);
    return make_float4(f0.x, f0.y, f1.x, f1.y);
}

// ---------------- aggregation: warp per node, CSR gather (fp16 source) ----------------
// bufB[n] = relu(dis[n] * (bufAh[n] + sum_{s} bufAh[s]) + bias); POOL: RED into sums.
template <bool POOL>
__global__ __launch_bounds__(256) void k_agg(const float* __restrict__ bias) {
    int gtid = blockIdx.x * blockDim.x + threadIdx.x;
    int warp = gtid >> 5;
    int lane = gtid & 31;
    int nw   = (gridDim.x * blockDim.x) >> 5;
    float4 b = *(const float4*)&bias[lane * 4];
    const int fo = lane * 4;   // feature offset

    for (int n = warp; n < N_NODES; n += nw) {
        int start = g_rowstart[n];
        int cnt   = g_ecnt[n];
        float4 acc = ldh4(&g_bufAh[(size_t)n * DIM + fo]);  // self loop

        int k = 0;
        for (; k + 8 <= cnt; k += 8) {
            int s0 = g_esrc[start + k + 0];
            int s1 = g_esrc[start + k + 1];
            int s2 = g_esrc[start + k + 2];
            int s3 = g_esrc[start + k + 3];
            int s4 = g_esrc[start + k + 4];
            int s5 = g_esrc[start + k + 5];
            int s6 = g_esrc[start + k + 6];
            int s7 = g_esrc[start + k + 7];
            float4 v0 = ldh4(&g_bufAh[(size_t)s0 * DIM + fo]);
            float4 v1 = ldh4(&g_bufAh[(size_t)s1 * DIM + fo]);
            float4 v2 = ldh4(&g_bufAh[(size_t)s2 * DIM + fo]);
            float4 v3 = ldh4(&g_bufAh[(size_t)s3 * DIM + fo]);
            float4 v4 = ldh4(&g_bufAh[(size_t)s4 * DIM + fo]);
            float4 v5 = ldh4(&g_bufAh[(size_t)s5 * DIM + fo]);
            float4 v6 = ldh4(&g_bufAh[(size_t)s6 * DIM + fo]);
            float4 v7 = ldh4(&g_bufAh[(size_t)s7 * DIM + fo]);
            acc.x += (v0.x + v1.x) + (v2.x + v3.x) + ((v4.x + v5.x) + (v6.x + v7.x));
            acc.y += (v0.y + v1.y) + (v2.y + v3.y) + ((v4.y + v5.y) + (v6.y + v7.y));
            acc.z += (v0.z + v1.z) + (v2.z + v3.z) + ((v4.z + v5.z) + (v6.z + v7.z));
            acc.w += (v0.w + v1.w) + (v2.w + v3.w) + ((v4.w + v5.w) + (v6.w + v7.w));
        }
        for (; k < cnt; k++) {
            int s = g_esrc[start + k];
            float4 v = ldh4(&g_bufAh[(size_t)s * DIM + fo]);
            acc.x += v.x; acc.y += v.y; acc.z += v.z; acc.w += v.w;
        }

        float di = rsqrtf((float)(cnt + 1));
        float4 o;
        o.x = fmaxf(fmaf(acc.x, di, b.x), 0.0f);
        o.y = fmaxf(fmaf(acc.y, di, b.y), 0.0f);
        o.z = fmaxf(fmaf(acc.z, di, b.z), 0.0f);
        o.w = fmaxf(fmaf(acc.w, di, b.w), 0.0f);
        *(float4*)&g_bufB[(size_t)n * DIM + fo] = o;

        if (POOL) {
            int g = g_batch[n];
            red_add_v4(&g_sums[g * DIM + fo], o);
        }
    }
}

// ---------------- final FC ----------------
__global__ void k_final(const float* __restrict__ Wfc, const float* __restrict__ bfc,
                        float* __restrict__ out) {
    int idx = blockIdx.x * blockDim.x + threadIdx.x;
    if (idx >= NG * OUTD) return;
    int g = idx / OUTD;
    int o = idx % OUTD;
    float inv = 1.0f / fmaxf(g_cnts[g], 1.0f);
    float acc = 0.0f;
#pragma unroll 8
    for (int h = 0; h < DIM; h++) acc += g_sums[g * DIM + h] * Wfc[h * OUTD + o];
    out[idx] = acc * inv + bfc[o];
}

// ---------------- launch ----------------
extern "C" void kernel_launch(void* const* d_in, const int* in_sizes, int n_in,
                              void* d_out, int out_size) {
    const float* x     = (const float*)d_in[0];
    const void*  ei    = d_in[1];
    const void*  batch = d_in[2];
    const float* W1    = (const float*)d_in[3];
    const float* b1    = (const float*)d_in[4];
    const float* W2    = (const float*)d_in[5];
    const float* b2    = (const float*)d_in[6];
    const float* Wfc   = (const float*)d_in[7];
    const float* bfc   = (const float*)d_in[8];
    float* out = (float*)d_out;

    const int gemm_blocks = (N_NODES + 127) / 128;   // 391 (static 44 KB smem)

    // fork-join: CSR build on side stream overlaps gemm1 on main stream.
    // Created per call, intentionally not destroyed while capture may be live
    // (kernel_launch runs only twice: correctness + capture; bounded leak).
    cudaStream_t s1;
    cudaStreamCreateWithFlags(&s1, cudaStreamNonBlocking);
    cudaEvent_t e1, e2;
    cudaEventCreateWithFlags(&e1, cudaEventDisableTiming);
    cudaEventCreateWithFlags(&e2, cudaEventDisableTiming);

    k_prep<<<64, 256>>>(ei, W1, W2);                    // 1: detect+zero+packW
    k_convert<<<1024, 256>>>(ei, batch);                // 2
    cudaEventRecord(e1, 0);
    cudaStreamWaitEvent(s1, e1, 0);
    k_scan1<<<NBLK, SCAN_B, 0, s1>>>();                 // 3 (side)
    k_gemm<<<gemm_blocks, 256>>>(x, 0);                 // 4 (main) <- profiled
    k_scan2<<<1, 32, 0, s1>>>();                        // 5 (side)
    k_cursor<<<196, 256, 0, s1>>>();                    // 6 (side)
    k_bucket<<<1024, 256, 0, s1>>>();                   // 7 (side)
    cudaEventRecord(e2, s1);
    cudaStreamWaitEvent(0, e2, 0);
    k_agg<false><<<2368, 256>>>(b1);                    // 8
    k_gemm<<<gemm_blocks, 256>>>(nullptr, 1);           // 9
    k_agg<true><<<2368, 256>>>(b2);                     // 10
    k_final<<<4, 256>>>(Wfc, bfc, out);                 // 11
}

// round 17
// speedup vs baseline: 1.3203x; 1.0461x over previous
#include <cuda_runtime.h>
#include <cuda_fp16.h>
#include <cstdint>

#define N_NODES 50000
#define N_EDGES 800000
#define DIM     128
#define NG      64
#define OUTD    16
#define SCAN_B  1024
#define NBLK    ((N_NODES + SCAN_B - 1) / SCAN_B)   // 49
#define WPACK_N 4096                                 // 8 kc16 * 16 nt * 32 lanes

// ---------------- scratch (static device globals; no allocation) ----------------
__device__ __align__(16) int   g_src[N_EDGES];
__device__ __align__(16) int   g_dst[N_EDGES];
__device__ __align__(16) int   g_esrc[N_EDGES];     // bucketed-by-dst src list
__device__ __align__(16) int   g_batch[N_NODES];
__device__ __align__(16) int   g_ecnt[N_NODES];     // in-degree (edges only)
__device__ __align__(16) int   g_off[N_NODES];      // block-local exclusive scan
__device__ __align__(16) int   g_rowstart[N_NODES]; // final CSR row start
__device__ __align__(16) int   g_cursor[N_NODES];   // bucket-fill cursors
__device__ int   g_bsum[NBLK];
__device__ int   g_bo[NBLK];
__device__ __align__(16)  uint2  g_Wpack[2 * WPACK_N];            // packed fp16 B frags
__device__ __align__(128) __half g_bufAh[(size_t)N_NODES * DIM];  // h*dis fp16 (gather src)
__device__ __align__(128) float  g_bufB[(size_t)N_NODES * DIM];   // layer output f32
__device__ __align__(16) float g_sums[NG * DIM];
__device__ __align__(16) float g_cnts[NG];
__device__ int g_is64;

// ---------------- fp16 mma helper ----------------
// m16n8k16, thread (g=lane>>2, t=lane&3):
//   a0={A[g][2t],A[g][2t+1]}  a1={A[g+8][2t],..}  a2={A[g][2t+8],..}  a3={A[g+8][2t+8],..}
//   b0={B[2t][n],B[2t+1][n]}  b1={B[2t+8][n],B[2t+9][n]}   (B row = k, n = nt*8+g)
//   c0,c1 = row g cols {2t,2t+1}; c2,c3 = row g+8
__device__ __forceinline__ void mma_f16(float& c0, float& c1, float& c2, float& c3,
                                        unsigned a0, unsigned a1, unsigned a2, unsigned a3,
                                        unsigned b0, unsigned b1) {
    asm volatile(
        "mma.sync.aligned.m16n8k16.row.col.f32.f16.f16.f32 "
        "{%0,%1,%2,%3}, {%4,%5,%6,%7}, {%8,%9}, {%0,%1,%2,%3};"
        : "+f"(c0), "+f"(c1), "+f"(c2), "+f"(c3)
        : "r"(a0), "r"(a1), "r"(a2), "r"(a3), "r"(b0), "r"(b1));
}

__device__ __forceinline__ unsigned pack_h2(float lo, float hi) {
    __half2 h = __floats2half2_rn(lo, hi);
    return *reinterpret_cast<unsigned*>(&h);
}

// ---------------- prep: dtype detect + zero counters + pack both W matrices (fp16 frags) ----------------
// Wpack[sel][(kc*16+nt)*32 + lane] = uint2{ h2(W[k0+2t][n],W[k0+2t+1][n]),
//                                           h2(W[k0+8+2t][n],W[k0+9+2t][n]) }, k0=kc*16, n=nt*8+g
__global__ void k_prep(const void* ei, const float* __restrict__ W1,
                       const float* __restrict__ W2) {
    int i  = blockIdx.x * blockDim.x + threadIdx.x;
    int st = gridDim.x * blockDim.x;
    if (i == 0) {
        const unsigned long long* p = (const unsigned long long*)ei;
        bool is64 = true;
        for (int j = 0; j < 8; j++)
            if (p[j] >= (unsigned long long)N_NODES) is64 = false;
        g_is64 = is64 ? 1 : 0;
    }
    for (int n = i; n < N_NODES; n += st) g_ecnt[n] = 0;
    for (int n = i; n < NG * DIM; n += st) g_sums[n] = 0.0f;
    for (int n = i; n < NG; n += st) g_cnts[n] = 0.0f;
    for (int j = i; j < 2 * WPACK_N; j += st) {
        int sel  = j >> 12;
        int idx  = j & (WPACK_N - 1);
        const float* W = sel ? W2 : W1;
        int lane = idx & 31;
        int nt   = (idx >> 5) & 15;
        int kc   = idx >> 9;            // 0..7
        int g = lane >> 2, t = lane & 3;
        int n  = nt * 8 + g;
        int k0 = kc * 16;
        uint2 b;
        b.x = pack_h2(W[(size_t)(k0 + 2 * t) * DIM + n],
                      W[(size_t)(k0 + 2 * t + 1) * DIM + n]);
        b.y = pack_h2(W[(size_t)(k0 + 8 + 2 * t) * DIM + n],
                      W[(size_t)(k0 + 9 + 2 * t) * DIM + n]);
        g_Wpack[j] = b;
    }
}

// ---------------- convert indices + degree histogram + graph counts ----------------
__global__ void k_convert(const void* ei, const void* batch) {
    int i  = blockIdx.x * blockDim.x + threadIdx.x;
    int st = gridDim.x * blockDim.x;
    const bool is64 = (g_is64 != 0);
    for (int e = i; e < N_EDGES; e += st) {
        int s, d;
        if (is64) {
            s = (int)((const long long*)ei)[e];
            d = (int)((const long long*)ei)[N_EDGES + e];
        } else {
            s = ((const int*)ei)[e];
            d = ((const int*)ei)[N_EDGES + e];
        }
        g_src[e] = s;
        g_dst[e] = d;
        atomicAdd(&g_ecnt[d], 1);
    }
    for (int n = i; n < N_NODES; n += st) {
        int b = is64 ? (int)((const long long*)batch)[n]
                     : ((const int*)batch)[n];
        g_batch[n] = b;
        atomicAdd(&g_cnts[b], 1.0f);
    }
}

// ---------------- scan phase 1: per-block exclusive scan of ecnt ----------------
__global__ __launch_bounds__(SCAN_B) void k_scan1() {
    __shared__ int sh[SCAN_B];
    int b = blockIdx.x, t = threadIdx.x;
    int i = b * SCAN_B + t;
    int v = (i < N_NODES) ? g_ecnt[i] : 0;
    sh[t] = v;
    __syncthreads();
    for (int s = 1; s < SCAN_B; s <<= 1) {
        int x = (t >= s) ? sh[t - s] : 0;
        __syncthreads();
        sh[t] += x;
        __syncthreads();
    }
    if (i < N_NODES) g_off[i] = sh[t] - v;   // exclusive
    if (t == SCAN_B - 1) g_bsum[b] = sh[t];
}

// ---------------- scan phase 2 ----------------
__global__ void k_scan2() {
    if (threadIdx.x == 0) {
        int a = 0;
        for (int i = 0; i < NBLK; i++) { g_bo[i] = a; a += g_bsum[i]; }
    }
}

// ---------------- final offsets + cursors ----------------
__global__ void k_cursor() {
    int i  = blockIdx.x * blockDim.x + threadIdx.x;
    int st = gridDim.x * blockDim.x;
    for (int n = i; n < N_NODES; n += st) {
        int base = g_off[n] + g_bo[n >> 10];
        g_rowstart[n] = base;
        g_cursor[n]   = base;
    }
}

// ---------------- bucket fill ----------------
__global__ void k_bucket() {
    int i  = blockIdx.x * blockDim.x + threadIdx.x;
    int st = gridDim.x * blockDim.x;
    for (int e = i; e < N_EDGES; e += st) {
        int d = g_dst[e];
        int pos = atomicAdd(&g_cursor[d], 1);
        g_esrc[pos] = g_src[e];
    }
}

// ---------------- GEMM: bufAh = fp16((A @ W) * dis[row])  (fp16 m16n8k16) ----------------
// 256 threads / 8 warps; block = 128 rows x 128 cols; warp = 16 rows (one m16 tile).
// __launch_bounds__(256, 2): cap at 128 regs -> 2 blocks/SM (16 warps; was 1 block/8 warps
// at 136 regs in R16 -- occupancy was the binding constraint, occ 12.1% / issue 8.9%).
// B: pre-packed fp16 frags (32 KB) staged coalesced; one LDS.64 per (kc,nt), conflict-free.
// A: staged as fp16 per k16 chunk, double-buffered; row stride 12 words ->
//    frag LDS banks {12g+t} mod 32 all distinct (conflict-free).
// Ain==nullptr -> read g_bufB (device-side symbol; host can't pass __device__ arrays).
#define A_STRIDE_W 12                 // 32-bit words per row-chunk (8 data + 4 pad)
#define A_BUF_W    (128 * A_STRIDE_W) // 1536 words per buffer
__global__ __launch_bounds__(256, 2) void k_gemm(const float* Ain, int wsel) {
    __shared__ uint2    Bf[WPACK_N];        // 32768 B
    __shared__ unsigned As[2 * A_BUF_W];    // 12288 B
    const float* A = Ain ? Ain : g_bufB;
    const int tid  = threadIdx.x;
    const int w    = tid >> 5;
    const int lane = tid & 31;
    const int g    = lane >> 2;
    const int t    = lane & 3;

    // stage packed B fragments once (fully coalesced copy); visible after first sync
    {
        const uint2* Wp = g_Wpack + wsel * WPACK_N;
#pragma unroll
        for (int i = 0; i < WPACK_N / 256; i++)
            Bf[tid + i * 256] = Wp[tid + i * 256];
    }

    const int rbase = blockIdx.x * 128;
    const int ra    = w * 16 + g;        // local row (upper half of m16 tile)
    const int r0 = rbase + ra;
    const int r1 = r0 + 8;
    const bool ok0 = r0 < N_NODES, ok1 = r1 < N_NODES;

    // A staging: thread -> (row = tid>>1, 8 floats at koff = (tid&1)*8) per k16 chunk
    const int srow  = tid >> 1;
    const int skoff = (tid & 1) * 8;
    const float* srcRow = A + (size_t)min(rbase + srow, N_NODES - 1) * DIM;
    const int stgOff = srow * A_STRIDE_W + (tid & 1) * 4;

    // frag base pointers (hoisted; fewer live regs in loop)
    const unsigned* fragLo = &As[ra * A_STRIDE_W];
    const unsigned* fragHi = &As[(ra + 8) * A_STRIDE_W];

    // prologue: chunk 0 -> buffer 0 (f32 -> fp16 at staging; one STS.128)
    {
        float4 f0 = *(const float4*)&srcRow[skoff];
        float4 f1 = *(const float4*)&srcRow[skoff + 4];
        uint4 pk;
        pk.x = pack_h2(f0.x, f0.y); pk.y = pack_h2(f0.z, f0.w);
        pk.z = pack_h2(f1.x, f1.y); pk.w = pack_h2(f1.z, f1.w);
        *(uint4*)&As[stgOff] = pk;
    }
    __syncthreads();

    float acc[16][4];
#pragma unroll
    for (int nt = 0; nt < 16; nt++)
#pragma unroll
        for (int j = 0; j < 4; j++) acc[nt][j] = 0.0f;

    for (int c = 0; c < 8; c++) {
        float4 f0, f1;
        if (c < 7) {
            f0 = *(const float4*)&srcRow[(c + 1) * 16 + skoff];
            f1 = *(const float4*)&srcRow[(c + 1) * 16 + skoff + 4];
        }
        const int boff = (c & 1) * A_BUF_W;
        // A fragments: 4 conflict-free LDS.32 (each = half2)
        unsigned a0 = fragLo[boff + t];
        unsigned a1 = fragHi[boff + t];
        unsigned a2 = fragLo[boff + 4 + t];
        unsigned a3 = fragHi[boff + 4 + t];
#pragma unroll
        for (int nt = 0; nt < 16; nt++) {
            uint2 b = Bf[(c * 16 + nt) * 32 + lane];   // LDS.64 conflict-free
            mma_f16(acc[nt][0], acc[nt][1], acc[nt][2], acc[nt][3],
                    a0, a1, a2, a3, b.x, b.y);
        }
        if (c < 7) {   // fill other buffer (its last reader finished at prev sync)
            uint4 pk;
            pk.x = pack_h2(f0.x, f0.y); pk.y = pack_h2(f0.z, f0.w);
            pk.z = pack_h2(f1.x, f1.y); pk.w = pack_h2(f1.z, f1.w);
            *(uint4*)&As[((c + 1) & 1) * A_BUF_W + stgOff] = pk;
        }
        __syncthreads();
    }

    // epilogue: scale by dis = rsqrt(ecnt+1), store fp16
    float d0 = ok0 ? rsqrtf((float)(g_ecnt[r0] + 1)) : 0.0f;
    float d1 = ok1 ? rsqrtf((float)(g_ecnt[r1] + 1)) : 0.0f;
#pragma unroll
    for (int nt = 0; nt < 16; nt++) {
        int col = nt * 8 + 2 * t;
        if (ok0) *(__half2*)&g_bufAh[(size_t)r0 * DIM + col] =
            __floats2half2_rn(acc[nt][0] * d0, acc[nt][1] * d0);
        if (ok1) *(__half2*)&g_bufAh[(size_t)r1 * DIM + col] =
            __floats2half2_rn(acc[nt][2] * d1, acc[nt][3] * d1);
    }
}

// ---------------- helpers ----------------
__device__ __forceinline__ void red_add_v4(float* p, float4 v) {
    unsigned long long gp = (unsigned long long)__cvta_generic_to_global(p);
    asm volatile("red.global.add.v4.f32 [%0], {%1,%2,%3,%4};"
                 :: "l"(gp), "f"(v.x), "f"(v.y), "f"(v.z), "f"(v.w)
                 : "memory");
}

__device__ __forceinline__ float4 ldh4(const __half* p) {
    uint2 u = *(const uint2*)p;    // 4 halves, one 8B load
    __half2 h0 = *reinterpret_cast<__half2*>(&u.x);
    __half2 h1 = *reinterpret_cast<__half2*>(&u.y);
    float2 f0 = __half22float2(h0);
    float2 f1 = __half22float2(h1);
    return make_float4(f0.x, f0.y, f1.x, f1.y);
}

// ---------------- aggregation: warp per node, CSR gather (fp16 source) ----------------
// bufB[n] = relu(dis[n] * (bufAh[n] + sum_{s} bufAh[s]) + bias); POOL: RED into sums.
template <bool POOL>
__global__ __launch_bounds__(256) void k_agg(const float* __restrict__ bias) {
    int gtid = blockIdx.x * blockDim.x + threadIdx.x;
    int warp = gtid >> 5;
    int lane = gtid & 31;
    int nw   = (gridDim.x * blockDim.x) >> 5;
    float4 b = *(const float4*)&bias[lane * 4];
    const int fo = lane * 4;   // feature offset

    for (int n = warp; n < N_NODES; n += nw) {
        int start = g_rowstart[n];
        int cnt   = g_ecnt[n];
        float4 acc = ldh4(&g_bufAh[(size_t)n * DIM + fo]);  // self loop

        int k = 0;
        for (; k + 8 <= cnt; k += 8) {
            int s0 = g_esrc[start + k + 0];
            int s1 = g_esrc[start + k + 1];
            int s2 = g_esrc[start + k + 2];
            int s3 = g_esrc[start + k + 3];
            int s4 = g_esrc[start + k + 4];
            int s5 = g_esrc[start + k + 5];
            int s6 = g_esrc[start + k + 6];
            int s7 = g_esrc[start + k + 7];
            float4 v0 = ldh4(&g_bufAh[(size_t)s0 * DIM + fo]);
            float4 v1 = ldh4(&g_bufAh[(size_t)s1 * DIM + fo]);
            float4 v2 = ldh4(&g_bufAh[(size_t)s2 * DIM + fo]);
            float4 v3 = ldh4(&g_bufAh[(size_t)s3 * DIM + fo]);
            float4 v4 = ldh4(&g_bufAh[(size_t)s4 * DIM + fo]);
            float4 v5 = ldh4(&g_bufAh[(size_t)s5 * DIM + fo]);
            float4 v6 = ldh4(&g_bufAh[(size_t)s6 * DIM + fo]);
            float4 v7 = ldh4(&g_bufAh[(size_t)s7 * DIM + fo]);
            acc.x += (v0.x + v1.x) + (v2.x + v3.x) + ((v4.x + v5.x) + (v6.x + v7.x));
            acc.y += (v0.y + v1.y) + (v2.y + v3.y) + ((v4.y + v5.y) + (v6.y + v7.y));
            acc.z += (v0.z + v1.z) + (v2.z + v3.z) + ((v4.z + v5.z) + (v6.z + v7.z));
            acc.w += (v0.w + v1.w) + (v2.w + v3.w) + ((v4.w + v5.w) + (v6.w + v7.w));
        }
        for (; k < cnt; k++) {
            int s = g_esrc[start + k];
            float4 v = ldh4(&g_bufAh[(size_t)s * DIM + fo]);
            acc.x += v.x; acc.y += v.y; acc.z += v.z; acc.w += v.w;
        }

        float di = rsqrtf((float)(cnt + 1));
        float4 o;
        o.x = fmaxf(fmaf(acc.x, di, b.x), 0.0f);
        o.y = fmaxf(fmaf(acc.y, di, b.y), 0.0f);
        o.z = fmaxf(fmaf(acc.z, di, b.z), 0.0f);
        o.w = fmaxf(fmaf(acc.w, di, b.w), 0.0f);
        *(float4*)&g_bufB[(size_t)n * DIM + fo] = o;

        if (POOL) {
            int g = g_batch[n];
            red_add_v4(&g_sums[g * DIM + fo], o);
        }
    }
}

// ---------------- final FC ----------------
__global__ void k_final(const float* __restrict__ Wfc, const float* __restrict__ bfc,
                        float* __restrict__ out) {
    int idx = blockIdx.x * blockDim.x + threadIdx.x;
    if (idx >= NG * OUTD) return;
    int g = idx / OUTD;
    int o = idx % OUTD;
    float inv = 1.0f / fmaxf(g_cnts[g], 1.0f);
    float acc = 0.0f;
#pragma unroll 8
    for (int h = 0; h < DIM; h++) acc += g_sums[g * DIM + h] * Wfc[h * OUTD + o];
    out[idx] = acc * inv + bfc[o];
}

// ---------------- launch ----------------
extern "C" void kernel_launch(void* const* d_in, const int* in_sizes, int n_in,
                              void* d_out, int out_size) {
    const float* x     = (const float*)d_in[0];
    const void*  ei    = d_in[1];
    const void*  batch = d_in[2];
    const float* W1    = (const float*)d_in[3];
    const float* b1    = (const float*)d_in[4];
    const float* W2    = (const float*)d_in[5];
    const float* b2    = (const float*)d_in[6];
    const float* Wfc   = (const float*)d_in[7];
    const float* bfc   = (const float*)d_in[8];
    float* out = (float*)d_out;

    const int gemm_blocks = (N_NODES + 127) / 128;   // 391 (static 44 KB smem)

    // fork-join: CSR build on side stream overlaps gemm1 on main stream.
    // Created per call, intentionally not destroyed while capture may be live
    // (kernel_launch runs only twice: correctness + capture; bounded leak).
    cudaStream_t s1;
    cudaStreamCreateWithFlags(&s1, cudaStreamNonBlocking);
    cudaEvent_t e1, e2;
    cudaEventCreateWithFlags(&e1, cudaEventDisableTiming);
    cudaEventCreateWithFlags(&e2, cudaEventDisableTiming);

    k_prep<<<64, 256>>>(ei, W1, W2);                    // 1: detect+zero+packW
    k_convert<<<1024, 256>>>(ei, batch);                // 2
    cudaEventRecord(e1, 0);
    cudaStreamWaitEvent(s1, e1, 0);
    k_scan1<<<NBLK, SCAN_B, 0, s1>>>();                 // 3 (side)
    k_gemm<<<gemm_blocks, 256>>>(x, 0);                 // 4 (main) <- profiled
    k_scan2<<<1, 32, 0, s1>>>();                        // 5 (side)
    k_cursor<<<196, 256, 0, s1>>>();                    // 6 (side)
    k_bucket<<<1024, 256, 0, s1>>>();                   // 7 (side)
    cudaEventRecord(e2, s1);
    cudaStreamWaitEvent(0, e2, 0);
    k_agg<false><<<2368, 256>>>(b1);                    // 8
    k_gemm<<<gemm_blocks, 256>>>(nullptr, 1);           // 9
    k_agg<true><<<2368, 256>>>(b2);                     // 10
    k_final<<<4, 256>>>(Wfc, bfc, out);                 // 11
}